// round 2
// baseline (speedup 1.0000x reference)
#include <cuda_runtime.h>
#include <cuda_bf16.h>
#include <cstddef>

// Problem constants (fixed by the dataset)
constexpr int N_   = 50000;
constexpr int E_   = 800000;
constexpr int INC  = 128;
constexpr int HID  = 32;
constexpr int HEADS = 8;
constexpr int F1   = HEADS * HID;   // 256
constexpr int OUTC = 64;
constexpr float NEG_SLOPE = 0.2f;

// ---------------- scratch (device globals: allocation-free) ----------------
__device__ float    g_h1[(size_t)N_ * F1];      // layer1 features  [N,256]
__device__ float    g_as1[N_ * HEADS];
__device__ float    g_ad1[N_ * HEADS];
__device__ float    g_e1[(size_t)E_ * HEADS];   // leaky-relu'd edge logits
__device__ unsigned g_m1[N_ * HEADS];           // encoded segment max
__device__ float    g_z1[N_ * HEADS];           // segment sum of exp
__device__ float    g_acc1[(size_t)N_ * F1];    // unnormalized message accum
__device__ float    g_hact[(size_t)N_ * F1];    // elu(layer1 out)  -> GEMM2 input
__device__ float    g_h2[(size_t)N_ * OUTC];
__device__ float    g_as2[N_];
__device__ float    g_ad2[N_];
__device__ float    g_e2[E_];
__device__ unsigned g_m2[N_];
__device__ float    g_z2[N_];
__device__ float    g_acc2[(size_t)N_ * OUTC];
__device__ int      g_src[E_];
__device__ int      g_dst[E_];
__device__ int      g_is64;                     // edge_index dtype flag

// order-preserving float<->uint encoding for atomicMax on floats
__device__ __forceinline__ unsigned enc_ord(float f) {
    unsigned b = __float_as_uint(f);
    return (b & 0x80000000u) ? ~b : (b | 0x80000000u);
}
__device__ __forceinline__ float dec_ord(unsigned u) {
    return (u & 0x80000000u) ? __uint_as_float(u & 0x7FFFFFFFu)
                             : __uint_as_float(~u);
}

// ---------------- zero scratch ----------------
__global__ void zero_scratch() {
    size_t i = (size_t)blockIdx.x * blockDim.x + threadIdx.x;
    size_t stride = (size_t)gridDim.x * blockDim.x;
    for (size_t j = i; j < (size_t)N_ * F1; j += stride) g_acc1[j] = 0.f;
    for (size_t j = i; j < (size_t)N_ * OUTC; j += stride) g_acc2[j] = 0.f;
    for (size_t j = i; j < (size_t)N_ * HEADS; j += stride) { g_z1[j] = 0.f; g_m1[j] = 0u; }
    for (size_t j = i; j < (size_t)N_; j += stride) { g_z2[j] = 0.f; g_m2[j] = 0u; }
}

// ---------------- edge dtype probe + int64/int32 -> int32 ------------------
// Safe under both layouts: only reads the first 128 bytes of the buffer.
__global__ void probe_edges(const int* __restrict__ ei32) {
    if (threadIdx.x == 0 && blockIdx.x == 0) {
        int all_hi_zero = 1;
        #pragma unroll
        for (int k = 0; k < 16; k++) {
            if (ei32[2 * k + 1] != 0) all_hi_zero = 0;
        }
        g_is64 = all_hi_zero;   // int64 little-endian with values < 2^31
    }
}

__global__ void conv_edges(const int* __restrict__ ei32) {
    int i = blockIdx.x * blockDim.x + threadIdx.x;
    if (i >= E_) return;
    if (g_is64) {
        g_src[i] = ei32[2 * (size_t)i];
        g_dst[i] = ei32[2 * ((size_t)E_ + i)];
    } else {
        g_src[i] = ei32[i];
        g_dst[i] = ei32[(size_t)E_ + i];
    }
}

// ---------------- simple tiled SGEMM: C[M,Ncol] = A[M,K] @ B[K,Ncol] -------
// BM=BN=64, BK=16, 256 threads, 4x4 per thread. K%16==0, Ncol%64==0 assumed.
__global__ void sgemm64(const float* __restrict__ A, const float* __restrict__ B,
                        float* __restrict__ C, int M, int K, int Ncol) {
    __shared__ float As[64][17];
    __shared__ float Bs[16][64];
    int tid = threadIdx.x;
    int row0 = blockIdx.y * 64, col0 = blockIdx.x * 64;
    int tm = (tid >> 4) << 2;
    int tn = (tid & 15) << 2;
    float acc[4][4] = {};

    for (int k0 = 0; k0 < K; k0 += 16) {
        // load A tile (64x16), 4 consecutive floats per thread
        {
            int base = tid * 4;
            int mm = base >> 4, kk = base & 15;
            float4 av;
            if (row0 + mm < M)
                av = *(const float4*)(A + (size_t)(row0 + mm) * K + k0 + kk);
            else
                av = make_float4(0.f, 0.f, 0.f, 0.f);
            As[mm][kk] = av.x; As[mm][kk + 1] = av.y;
            As[mm][kk + 2] = av.z; As[mm][kk + 3] = av.w;
        }
        // load B tile (16x64)
        {
            int base = tid * 4;
            int kk = base >> 6, nn = base & 63;
            float4 bv = *(const float4*)(B + (size_t)(k0 + kk) * Ncol + col0 + nn);
            *(float4*)&Bs[kk][nn] = bv;
        }
        __syncthreads();
        #pragma unroll
        for (int kk = 0; kk < 16; kk++) {
            float a0 = As[tm][kk], a1 = As[tm + 1][kk], a2 = As[tm + 2][kk], a3 = As[tm + 3][kk];
            float b0 = Bs[kk][tn], b1 = Bs[kk][tn + 1], b2 = Bs[kk][tn + 2], b3 = Bs[kk][tn + 3];
            acc[0][0] += a0 * b0; acc[0][1] += a0 * b1; acc[0][2] += a0 * b2; acc[0][3] += a0 * b3;
            acc[1][0] += a1 * b0; acc[1][1] += a1 * b1; acc[1][2] += a1 * b2; acc[1][3] += a1 * b3;
            acc[2][0] += a2 * b0; acc[2][1] += a2 * b1; acc[2][2] += a2 * b2; acc[2][3] += a2 * b3;
            acc[3][0] += a3 * b0; acc[3][1] += a3 * b1; acc[3][2] += a3 * b2; acc[3][3] += a3 * b3;
        }
        __syncthreads();
    }
    #pragma unroll
    for (int i = 0; i < 4; i++) {
        int r = row0 + tm + i;
        if (r < M) {
            float4 v = make_float4(acc[i][0], acc[i][1], acc[i][2], acc[i][3]);
            *(float4*)(C + (size_t)r * Ncol + col0 + tn) = v;
        }
    }
}

// ---------------- per-node attention coefficients, layer 1 ----------------
__global__ void alpha1_kernel(const float* __restrict__ a_src,
                              const float* __restrict__ a_dst) {
    int i = blockIdx.x * blockDim.x + threadIdx.x;
    if (i >= N_ * HEADS) return;
    int n = i >> 3, h = i & 7;
    const float4* hp = (const float4*)(g_h1 + (size_t)n * F1 + h * HID);
    const float4* sp = (const float4*)(a_src + h * HID);
    const float4* dp = (const float4*)(a_dst + h * HID);
    float s = 0.f, d = 0.f;
    #pragma unroll
    for (int q = 0; q < HID / 4; q++) {
        float4 hv = hp[q], sv = sp[q], dv = dp[q];
        s += hv.x * sv.x + hv.y * sv.y + hv.z * sv.z + hv.w * sv.w;
        d += hv.x * dv.x + hv.y * dv.y + hv.z * dv.z + hv.w * dv.w;
    }
    g_as1[i] = s; g_ad1[i] = d;
}

// ---------------- edge pass 1 (layer1): logits + segment max --------------
__global__ void edge_max1() {
    int e = blockIdx.x * blockDim.x + threadIdx.x;
    if (e >= E_) return;
    int s = g_src[e], d = g_dst[e];
    float ev[8];
    {
        float4 s0 = *(const float4*)(g_as1 + s * 8);
        float4 s1 = *(const float4*)(g_as1 + s * 8 + 4);
        float4 d0 = *(const float4*)(g_ad1 + d * 8);
        float4 d1 = *(const float4*)(g_ad1 + d * 8 + 4);
        ev[0] = s0.x + d0.x; ev[1] = s0.y + d0.y; ev[2] = s0.z + d0.z; ev[3] = s0.w + d0.w;
        ev[4] = s1.x + d1.x; ev[5] = s1.y + d1.y; ev[6] = s1.z + d1.z; ev[7] = s1.w + d1.w;
    }
    #pragma unroll
    for (int h = 0; h < 8; h++) {
        float v = ev[h];
        v = (v >= 0.f) ? v : NEG_SLOPE * v;
        ev[h] = v;
        atomicMax(&g_m1[d * 8 + h], enc_ord(v));
    }
    *(float4*)(g_e1 + (size_t)e * 8)     = make_float4(ev[0], ev[1], ev[2], ev[3]);
    *(float4*)(g_e1 + (size_t)e * 8 + 4) = make_float4(ev[4], ev[5], ev[6], ev[7]);
}

// ---------------- edge pass 2 (layer1): exp, z, unnormalized messages -----
// one warp per edge: lane handles channel (h*32 + lane) for all 8 heads
__global__ void edge_msg1() {
    int gw = (blockIdx.x * blockDim.x + threadIdx.x) >> 5;
    if (gw >= E_) return;
    int lane = threadIdx.x & 31;
    int s = g_src[gw], d = g_dst[gw];
    float w = 0.f;
    if (lane < 8) {
        float ev = g_e1[(size_t)gw * 8 + lane];
        float mv = dec_ord(g_m1[d * 8 + lane]);
        w = __expf(ev - mv);
        atomicAdd(&g_z1[d * 8 + lane], w);
    }
    const float* hs = g_h1 + (size_t)s * F1;
    float* ac = g_acc1 + (size_t)d * F1;
    #pragma unroll
    for (int h = 0; h < 8; h++) {
        float wh = __shfl_sync(0xffffffffu, w, h);
        int c = (h << 5) + lane;
        atomicAdd(ac + c, hs[c] * wh);
    }
}

// ---------------- node epilogue layer1: normalize + bias + ELU ------------
__global__ void node1(const float* __restrict__ b1) {
    int i = blockIdx.x * blockDim.x + threadIdx.x;
    if (i >= N_ * F1) return;
    int n = i >> 8, c = i & 255, h = c >> 5;
    float z = g_z1[n * 8 + h];
    float v = (z > 0.f) ? (g_acc1[i] / z) : 0.f;
    v += b1[c];
    g_hact[i] = (v > 0.f) ? v : (__expf(v) - 1.f);   // ELU alpha=1
}

// ---------------- per-node attention coefficients, layer 2 ----------------
__global__ void alpha2_kernel(const float* __restrict__ a_src,
                              const float* __restrict__ a_dst) {
    int n = blockIdx.x * blockDim.x + threadIdx.x;
    if (n >= N_) return;
    const float4* hp = (const float4*)(g_h2 + (size_t)n * OUTC);
    const float4* sp = (const float4*)a_src;
    const float4* dp = (const float4*)a_dst;
    float s = 0.f, d = 0.f;
    #pragma unroll
    for (int q = 0; q < OUTC / 4; q++) {
        float4 hv = hp[q], sv = sp[q], dv = dp[q];
        s += hv.x * sv.x + hv.y * sv.y + hv.z * sv.z + hv.w * sv.w;
        d += hv.x * dv.x + hv.y * dv.y + hv.z * dv.z + hv.w * dv.w;
    }
    g_as2[n] = s; g_ad2[n] = d;
}

__global__ void edge_max2() {
    int e = blockIdx.x * blockDim.x + threadIdx.x;
    if (e >= E_) return;
    int s = g_src[e], d = g_dst[e];
    float v = g_as2[s] + g_ad2[d];
    v = (v >= 0.f) ? v : NEG_SLOPE * v;
    g_e2[e] = v;
    atomicMax(&g_m2[d], enc_ord(v));
}

// one warp per edge, 64 channels -> 2 per lane
__global__ void edge_msg2() {
    int gw = (blockIdx.x * blockDim.x + threadIdx.x) >> 5;
    if (gw >= E_) return;
    int lane = threadIdx.x & 31;
    int s = g_src[gw], d = g_dst[gw];
    float w = 0.f;
    if (lane == 0) {
        w = __expf(g_e2[gw] - dec_ord(g_m2[d]));
        atomicAdd(&g_z2[d], w);
    }
    w = __shfl_sync(0xffffffffu, w, 0);
    const float* hs = g_h2 + (size_t)s * OUTC;
    float* ac = g_acc2 + (size_t)d * OUTC;
    atomicAdd(ac + lane,      hs[lane]      * w);
    atomicAdd(ac + 32 + lane, hs[32 + lane] * w);
}

__global__ void node2(const float* __restrict__ b2, float* __restrict__ out) {
    int i = blockIdx.x * blockDim.x + threadIdx.x;
    if (i >= N_ * OUTC) return;
    int n = i >> 6, c = i & 63;
    float z = g_z2[n];
    float v = (z > 0.f) ? (g_acc2[i] / z) : 0.f;
    out[i] = v + b2[c];
}

// ---------------- launch ----------------
extern "C" void kernel_launch(void* const* d_in, const int* in_sizes, int n_in,
                              void* d_out, int out_size) {
    const float* x    = (const float*)d_in[0];
    const int*   ei32 = (const int*)d_in[1];      // int32 view, layout probed on device
    const float* W1   = (const float*)d_in[2];
    const float* a1s  = (const float*)d_in[3];
    const float* a1d  = (const float*)d_in[4];
    const float* b1   = (const float*)d_in[5];
    const float* W2   = (const float*)d_in[6];
    const float* a2s  = (const float*)d_in[7];
    const float* a2d  = (const float*)d_in[8];
    const float* b2   = (const float*)d_in[9];
    float* out = (float*)d_out;

    void* p;
    cudaGetSymbolAddress(&p, g_h1);   float* h1   = (float*)p;
    cudaGetSymbolAddress(&p, g_hact); float* hact = (float*)p;
    cudaGetSymbolAddress(&p, g_h2);   float* h2   = (float*)p;

    zero_scratch<<<2048, 256>>>();
    probe_edges<<<1, 32>>>(ei32);
    conv_edges<<<(E_ + 255) / 256, 256>>>(ei32);

    // layer 1
    {
        dim3 grid(F1 / 64, (N_ + 63) / 64);
        sgemm64<<<grid, 256>>>(x, W1, h1, N_, INC, F1);
    }
    alpha1_kernel<<<(N_ * HEADS + 255) / 256, 256>>>(a1s, a1d);
    edge_max1<<<(E_ + 255) / 256, 256>>>();
    edge_msg1<<<(E_ * 32) / 256, 256>>>();
    node1<<<(N_ * F1) / 256, 256>>>(b1);

    // layer 2
    {
        dim3 grid(OUTC / 64, (N_ + 63) / 64);
        sgemm64<<<grid, 256>>>(hact, W2, h2, N_, F1, OUTC);
    }
    alpha2_kernel<<<(N_ + 255) / 256, 256>>>(a2s, a2d);
    edge_max2<<<(E_ + 255) / 256, 256>>>();
    edge_msg2<<<(E_ * 32) / 256, 256>>>();
    node2<<<(N_ * OUTC) / 256, 256>>>(b2, out);
}

// round 3
// speedup vs baseline: 1.7927x; 1.7927x over previous
#include <cuda_runtime.h>
#include <cuda_bf16.h>
#include <cstddef>

constexpr int N_   = 50000;
constexpr int E_   = 800000;
constexpr int INC  = 128;
constexpr int HID  = 32;
constexpr int HEADS = 8;
constexpr int F1   = HEADS * HID;   // 256
constexpr int OUTC = 64;
constexpr float NEG_SLOPE = 0.2f;

// ---------------- scratch ----------------
__device__ float g_h1[(size_t)N_ * F1];     // layer1 GEMM out
__device__ float g_as1[N_ * HEADS];
__device__ float g_ad1[N_ * HEADS];
__device__ float g_hact[(size_t)N_ * F1];   // elu(layer1) -> GEMM2 input
__device__ float g_h2[(size_t)N_ * OUTC];
__device__ float g_as2[N_];
__device__ float g_ad2[N_];
__device__ int   g_src[E_];
__device__ int   g_dst[E_];
__device__ int   g_deg[N_];
__device__ int   g_roff[N_ + 1];
__device__ int   g_cursor[N_];
__device__ int   g_csr_src[E_];
__device__ int   g_is64;

// ---------------- init ----------------
__global__ void zero_deg() {
    int i = blockIdx.x * blockDim.x + threadIdx.x;
    if (i < N_) g_deg[i] = 0;
}

// probe edge dtype: safe under both layouts (reads first 128 bytes only)
__global__ void probe_edges(const int* __restrict__ ei32) {
    if (threadIdx.x == 0 && blockIdx.x == 0) {
        int all_hi_zero = 1;
        #pragma unroll
        for (int k = 0; k < 16; k++)
            if (ei32[2 * k + 1] != 0) all_hi_zero = 0;
        g_is64 = all_hi_zero;
    }
}

__global__ void conv_edges(const int* __restrict__ ei32) {
    int i = blockIdx.x * blockDim.x + threadIdx.x;
    if (i >= E_) return;
    int s, d;
    if (g_is64) {
        s = ei32[2 * (size_t)i];
        d = ei32[2 * ((size_t)E_ + i)];
    } else {
        s = ei32[i];
        d = ei32[(size_t)E_ + i];
    }
    g_src[i] = s;
    g_dst[i] = d;
    atomicAdd(&g_deg[d], 1);
}

// single-block exclusive scan of degrees -> row offsets + cursors
__global__ void scan_deg() {
    __shared__ int tsum[1024];
    int tid = threadIdx.x;
    const int CH = (N_ + 1023) / 1024;          // 49
    int start = tid * CH;
    int end   = min(start + CH, N_);
    int s = 0;
    for (int i = start; i < end; i++) s += g_deg[i];
    tsum[tid] = s;
    __syncthreads();
    for (int off = 1; off < 1024; off <<= 1) {
        int v = (tid >= off) ? tsum[tid - off] : 0;
        __syncthreads();
        tsum[tid] += v;
        __syncthreads();
    }
    int base = (tid == 0) ? 0 : tsum[tid - 1];  // exclusive prefix
    for (int i = start; i < end; i++) {
        g_roff[i] = base;
        g_cursor[i] = base;
        base += g_deg[i];
    }
    if (tid == 1023) g_roff[N_] = base;
}

__global__ void build_csr() {
    int e = blockIdx.x * blockDim.x + threadIdx.x;
    if (e >= E_) return;
    int d = g_dst[e];
    int pos = atomicAdd(&g_cursor[d], 1);
    g_csr_src[pos] = g_src[e];
}

// ---------------- SGEMM 128x64 tiles, 8x4 per thread -------------------
__global__ void sgemm128x64(const float* __restrict__ A, const float* __restrict__ B,
                            float* __restrict__ C, int M, int K, int Ncol) {
    __shared__ float As[16][132];   // [k][m], padded
    __shared__ float Bs[16][68];    // [k][n], padded
    int tid  = threadIdx.x;
    int row0 = blockIdx.y * 128, col0 = blockIdx.x * 64;
    int tm = (tid >> 4) << 3;       // 0..120 step 8
    int tn = (tid & 15) << 2;       // 0..60 step 4
    float acc[8][4] = {};

    for (int k0 = 0; k0 < K; k0 += 16) {
        // A tile: 128x16, each thread 8 floats = 2 float4 along k
        {
            int base = tid * 8;
            int mm = base >> 4, kk = base & 15;   // kk in {0,8}
            int r = row0 + mm;
            float4 a0 = make_float4(0.f, 0.f, 0.f, 0.f), a1 = a0;
            if (r < M) {
                a0 = *(const float4*)(A + (size_t)r * K + k0 + kk);
                a1 = *(const float4*)(A + (size_t)r * K + k0 + kk + 4);
            }
            As[kk + 0][mm] = a0.x; As[kk + 1][mm] = a0.y;
            As[kk + 2][mm] = a0.z; As[kk + 3][mm] = a0.w;
            As[kk + 4][mm] = a1.x; As[kk + 5][mm] = a1.y;
            As[kk + 6][mm] = a1.z; As[kk + 7][mm] = a1.w;
        }
        // B tile: 16x64, each thread 1 float4
        {
            int base = tid * 4;
            int kk = base >> 6, nn = base & 63;
            float4 bv = *(const float4*)(B + (size_t)(k0 + kk) * Ncol + col0 + nn);
            Bs[kk][nn] = bv.x; Bs[kk][nn + 1] = bv.y;
            Bs[kk][nn + 2] = bv.z; Bs[kk][nn + 3] = bv.w;
        }
        __syncthreads();
        #pragma unroll
        for (int kk = 0; kk < 16; kk++) {
            float4 a0 = *(const float4*)&As[kk][tm];
            float4 a1 = *(const float4*)&As[kk][tm + 4];
            float4 bv = *(const float4*)&Bs[kk][tn];
            float a[8] = {a0.x, a0.y, a0.z, a0.w, a1.x, a1.y, a1.z, a1.w};
            float b[4] = {bv.x, bv.y, bv.z, bv.w};
            #pragma unroll
            for (int i = 0; i < 8; i++)
                #pragma unroll
                for (int j = 0; j < 4; j++)
                    acc[i][j] += a[i] * b[j];
        }
        __syncthreads();
    }
    #pragma unroll
    for (int i = 0; i < 8; i++) {
        int r = row0 + tm + i;
        if (r < M) {
            float4 v = make_float4(acc[i][0], acc[i][1], acc[i][2], acc[i][3]);
            *(float4*)(C + (size_t)r * Ncol + col0 + tn) = v;
        }
    }
}

// ---------------- per-node attention coefficients ----------------
__global__ void alpha1_kernel(const float* __restrict__ a_src,
                              const float* __restrict__ a_dst) {
    int i = blockIdx.x * blockDim.x + threadIdx.x;
    if (i >= N_ * HEADS) return;
    int n = i >> 3, h = i & 7;
    const float4* hp = (const float4*)(g_h1 + (size_t)n * F1 + h * HID);
    const float4* sp = (const float4*)(a_src + h * HID);
    const float4* dp = (const float4*)(a_dst + h * HID);
    float s = 0.f, d = 0.f;
    #pragma unroll
    for (int q = 0; q < HID / 4; q++) {
        float4 hv = hp[q], sv = sp[q], dv = dp[q];
        s += hv.x * sv.x + hv.y * sv.y + hv.z * sv.z + hv.w * sv.w;
        d += hv.x * dv.x + hv.y * dv.y + hv.z * dv.z + hv.w * dv.w;
    }
    g_as1[i] = s; g_ad1[i] = d;
}

__global__ void alpha2_kernel(const float* __restrict__ a_src,
                              const float* __restrict__ a_dst) {
    int n = blockIdx.x * blockDim.x + threadIdx.x;
    if (n >= N_) return;
    const float4* hp = (const float4*)(g_h2 + (size_t)n * OUTC);
    const float4* sp = (const float4*)a_src;
    const float4* dp = (const float4*)a_dst;
    float s = 0.f, d = 0.f;
    #pragma unroll
    for (int q = 0; q < OUTC / 4; q++) {
        float4 hv = hp[q], sv = sp[q], dv = dp[q];
        s += hv.x * sv.x + hv.y * sv.y + hv.z * sv.z + hv.w * sv.w;
        d += hv.x * dv.x + hv.y * dv.y + hv.z * dv.z + hv.w * dv.w;
    }
    g_as2[n] = s; g_ad2[n] = d;
}

// ---------------- CSR aggregation layer 1: one warp per dst node ----------
// lane owns channels c = lane*8 + q (q=0..7) -> head h = lane>>2 (fixed/lane)
// softmax without max-shift: shift-invariant; logits are O(1) here (no overflow)
__global__ void aggregate1(const float* __restrict__ b1) {
    __shared__ int   ss[8][32];
    __shared__ float ws[8][32][8];
    int w = (blockIdx.x * blockDim.x + threadIdx.x) >> 5;
    if (w >= N_) return;
    int lane = threadIdx.x & 31;
    int wb   = (threadIdx.x >> 5) & 7;
    int beg = g_roff[w], end = g_roff[w + 1];

    float ad[8];
    {
        float4 d0 = *(const float4*)(g_ad1 + w * 8);
        float4 d1 = *(const float4*)(g_ad1 + w * 8 + 4);
        ad[0] = d0.x; ad[1] = d0.y; ad[2] = d0.z; ad[3] = d0.w;
        ad[4] = d1.x; ad[5] = d1.y; ad[6] = d1.z; ad[7] = d1.w;
    }

    float acc[8] = {};
    float zp[8]  = {};

    for (int base = beg; base < end; base += 32) {
        int cnt = min(32, end - base);
        __syncwarp();   // WAR vs previous chunk's reads
        if (base + lane < end) {
            int s = g_csr_src[base + lane];
            ss[wb][lane] = s;
            float4 s0 = *(const float4*)(g_as1 + s * 8);
            float4 s1 = *(const float4*)(g_as1 + s * 8 + 4);
            float ev[8] = {s0.x + ad[0], s0.y + ad[1], s0.z + ad[2], s0.w + ad[3],
                           s1.x + ad[4], s1.y + ad[5], s1.z + ad[6], s1.w + ad[7]};
            #pragma unroll
            for (int h = 0; h < 8; h++) {
                float e = ev[h];
                e = (e >= 0.f) ? e : NEG_SLOPE * e;
                float wv = __expf(e);
                ws[wb][lane][h] = wv;
                zp[h] += wv;
            }
        }
        __syncwarp();
        for (int j = 0; j < cnt; j++) {
            int s = ss[wb][j];
            float wj = ws[wb][j][lane >> 2];
            const float* hs = g_h1 + (size_t)s * F1 + lane * 8;
            float4 p0 = *(const float4*)hs;
            float4 p1 = *(const float4*)(hs + 4);
            acc[0] += wj * p0.x; acc[1] += wj * p0.y;
            acc[2] += wj * p0.z; acc[3] += wj * p0.w;
            acc[4] += wj * p1.x; acc[5] += wj * p1.y;
            acc[6] += wj * p1.z; acc[7] += wj * p1.w;
        }
    }

    // reduce z across warp (all 8 heads)
    #pragma unroll
    for (int h = 0; h < 8; h++)
        #pragma unroll
        for (int off = 16; off > 0; off >>= 1)
            zp[h] += __shfl_xor_sync(0xffffffffu, zp[h], off);
    float zu = zp[0];
    #pragma unroll
    for (int h = 1; h < 8; h++)
        if ((lane >> 2) == h) zu = zp[h];

    float inv = (zu > 0.f) ? (1.f / zu) : 0.f;
    const float* bp = b1 + lane * 8;
    float4 b0 = *(const float4*)bp;
    float4 b1v = *(const float4*)(bp + 4);
    float bb[8] = {b0.x, b0.y, b0.z, b0.w, b1v.x, b1v.y, b1v.z, b1v.w};
    float o[8];
    #pragma unroll
    for (int q = 0; q < 8; q++) {
        float v = acc[q] * inv + bb[q];
        o[q] = (v > 0.f) ? v : (__expf(v) - 1.f);   // ELU
    }
    float* op = g_hact + (size_t)w * F1 + lane * 8;
    *(float4*)op       = make_float4(o[0], o[1], o[2], o[3]);
    *(float4*)(op + 4) = make_float4(o[4], o[5], o[6], o[7]);
}

// ---------------- CSR aggregation layer 2: one warp per dst node ----------
// lane owns channels c = lane*2, lane*2+1
__global__ void aggregate2(const float* __restrict__ b2, float* __restrict__ out) {
    __shared__ int   ss[8][32];
    __shared__ float ws[8][32];
    int w = (blockIdx.x * blockDim.x + threadIdx.x) >> 5;
    if (w >= N_) return;
    int lane = threadIdx.x & 31;
    int wb   = (threadIdx.x >> 5) & 7;
    int beg = g_roff[w], end = g_roff[w + 1];
    float adn = g_ad2[w];

    float acc0 = 0.f, acc1 = 0.f, zp = 0.f;

    for (int base = beg; base < end; base += 32) {
        int cnt = min(32, end - base);
        __syncwarp();
        if (base + lane < end) {
            int s = g_csr_src[base + lane];
            ss[wb][lane] = s;
            float e = g_as2[s] + adn;
            e = (e >= 0.f) ? e : NEG_SLOPE * e;
            float wv = __expf(e);
            ws[wb][lane] = wv;
            zp += wv;
        }
        __syncwarp();
        for (int j = 0; j < cnt; j++) {
            int s = ss[wb][j];
            float wj = ws[wb][j];
            float2 hv = *(const float2*)(g_h2 + (size_t)s * OUTC + lane * 2);
            acc0 += wj * hv.x;
            acc1 += wj * hv.y;
        }
    }
    #pragma unroll
    for (int off = 16; off > 0; off >>= 1)
        zp += __shfl_xor_sync(0xffffffffu, zp, off);
    float inv = (zp > 0.f) ? (1.f / zp) : 0.f;
    float2 bv = *(const float2*)(b2 + lane * 2);
    float2 ov = make_float2(acc0 * inv + bv.x, acc1 * inv + bv.y);
    *(float2*)(out + (size_t)w * OUTC + lane * 2) = ov;
}

// ---------------- launch ----------------
extern "C" void kernel_launch(void* const* d_in, const int* in_sizes, int n_in,
                              void* d_out, int out_size) {
    const float* x    = (const float*)d_in[0];
    const int*   ei32 = (const int*)d_in[1];
    const float* W1   = (const float*)d_in[2];
    const float* a1s  = (const float*)d_in[3];
    const float* a1d  = (const float*)d_in[4];
    const float* b1   = (const float*)d_in[5];
    const float* W2   = (const float*)d_in[6];
    const float* a2s  = (const float*)d_in[7];
    const float* a2d  = (const float*)d_in[8];
    const float* b2   = (const float*)d_in[9];
    float* out = (float*)d_out;

    void* p;
    cudaGetSymbolAddress(&p, g_h1);   float* h1   = (float*)p;
    cudaGetSymbolAddress(&p, g_hact); float* hact = (float*)p;
    cudaGetSymbolAddress(&p, g_h2);   float* h2   = (float*)p;

    // graph build (CSR)
    zero_deg<<<(N_ + 1023) / 1024, 1024>>>();
    probe_edges<<<1, 32>>>(ei32);
    conv_edges<<<(E_ + 255) / 256, 256>>>(ei32);
    scan_deg<<<1, 1024>>>();
    build_csr<<<(E_ + 255) / 256, 256>>>();

    // layer 1
    {
        dim3 grid(F1 / 64, (N_ + 127) / 128);
        sgemm128x64<<<grid, 256>>>(x, W1, h1, N_, INC, F1);
    }
    alpha1_kernel<<<(N_ * HEADS + 255) / 256, 256>>>(a1s, a1d);
    aggregate1<<<(N_ * 32 + 255) / 256, 256>>>(b1);

    // layer 2
    {
        dim3 grid(OUTC / 64, (N_ + 127) / 128);
        sgemm128x64<<<grid, 256>>>(hact, W2, h2, N_, F1, OUTC);
    }
    alpha2_kernel<<<(N_ + 255) / 256, 256>>>(a2s, a2d);
    aggregate2<<<(N_ * 32 + 255) / 256, 256>>>(b2, out);
}

// round 4
// speedup vs baseline: 2.1824x; 1.2174x over previous
#include <cuda_runtime.h>
#include <cuda_bf16.h>
#include <cstddef>

constexpr int N_   = 50000;
constexpr int E_   = 800000;
constexpr int INC  = 128;
constexpr int HID  = 32;
constexpr int HEADS = 8;
constexpr int F1   = HEADS * HID;   // 256
constexpr int OUTC = 64;
constexpr float NEG_SLOPE = 0.2f;
constexpr int NB_SCAN = (N_ + 255) / 256;   // 196 scan blocks

// ---------------- scratch ----------------
__device__ float g_h1[(size_t)N_ * F1];     // layer1 GEMM out
__device__ float g_as1[N_ * HEADS];
__device__ float g_ad1[N_ * HEADS];
__device__ float g_hact[(size_t)N_ * F1];   // elu(layer1) -> GEMM2 input
__device__ float g_h2[(size_t)N_ * OUTC];
__device__ float g_as2[N_];
__device__ float g_ad2[N_];
__device__ int   g_src[E_];
__device__ int   g_dst[E_];
__device__ int   g_deg[N_];
__device__ int   g_roff[N_ + 1];
__device__ int   g_cursor[N_];
__device__ int   g_csr_src[E_];
__device__ int   g_bsum[NB_SCAN];
__device__ int   g_boff[NB_SCAN];
__device__ int   g_is64;

// ---------------- init ----------------
__global__ void zero_deg() {
    int i = blockIdx.x * blockDim.x + threadIdx.x;
    if (i < N_) g_deg[i] = 0;
}

// probe edge dtype: safe under both layouts (reads first 128 bytes only)
__global__ void probe_edges(const int* __restrict__ ei32) {
    if (threadIdx.x == 0 && blockIdx.x == 0) {
        int all_hi_zero = 1;
        #pragma unroll
        for (int k = 0; k < 16; k++)
            if (ei32[2 * k + 1] != 0) all_hi_zero = 0;
        g_is64 = all_hi_zero;
    }
}

__global__ void conv_edges(const int* __restrict__ ei32) {
    int i = blockIdx.x * blockDim.x + threadIdx.x;
    if (i >= E_) return;
    int s, d;
    if (g_is64) {
        s = ei32[2 * (size_t)i];
        d = ei32[2 * ((size_t)E_ + i)];
    } else {
        s = ei32[i];
        d = ei32[(size_t)E_ + i];
    }
    g_src[i] = s;
    g_dst[i] = d;
    atomicAdd(&g_deg[d], 1);
}

// ---------------- 3-phase grid scan of degrees ----------------
// phase 1: per-block exclusive scan (256 elems/block) + block sums
__global__ void scan_p1() {
    __shared__ int sh[256];
    int i = blockIdx.x * 256 + threadIdx.x;
    int v = (i < N_) ? g_deg[i] : 0;
    sh[threadIdx.x] = v;
    __syncthreads();
    #pragma unroll
    for (int off = 1; off < 256; off <<= 1) {
        int t = (threadIdx.x >= off) ? sh[threadIdx.x - off] : 0;
        __syncthreads();
        sh[threadIdx.x] += t;
        __syncthreads();
    }
    if (i < N_) g_roff[i] = sh[threadIdx.x] - v;          // exclusive
    if (threadIdx.x == 255) g_bsum[blockIdx.x] = sh[255]; // block total
}

// phase 2: single small block scans the 196 block sums
__global__ void scan_p2() {
    __shared__ int sh[256];
    int v = (threadIdx.x < NB_SCAN) ? g_bsum[threadIdx.x] : 0;
    sh[threadIdx.x] = v;
    __syncthreads();
    #pragma unroll
    for (int off = 1; off < 256; off <<= 1) {
        int t = (threadIdx.x >= off) ? sh[threadIdx.x - off] : 0;
        __syncthreads();
        sh[threadIdx.x] += t;
        __syncthreads();
    }
    if (threadIdx.x < NB_SCAN) g_boff[threadIdx.x] = sh[threadIdx.x] - v;
    if (threadIdx.x == 255) g_roff[N_] = sh[255];         // total == E_
}

// phase 3: add block offsets, fill cursors
__global__ void scan_p3() {
    int i = blockIdx.x * 256 + threadIdx.x;
    if (i >= N_) return;
    int r = g_roff[i] + g_boff[blockIdx.x];
    g_roff[i] = r;
    g_cursor[i] = r;
}

__global__ void build_csr() {
    int e = blockIdx.x * blockDim.x + threadIdx.x;
    if (e >= E_) return;
    int d = g_dst[e];
    int pos = atomicAdd(&g_cursor[d], 1);
    g_csr_src[pos] = g_src[e];
}

// ---------------- SGEMM 128x64 tiles, 8x4 per thread -------------------
__global__ void sgemm128x64(const float* __restrict__ A, const float* __restrict__ B,
                            float* __restrict__ C, int M, int K, int Ncol) {
    __shared__ float As[16][132];   // [k][m], padded
    __shared__ float Bs[16][68];    // [k][n], padded
    int tid  = threadIdx.x;
    int row0 = blockIdx.y * 128, col0 = blockIdx.x * 64;
    int tm = (tid >> 4) << 3;       // 0..120 step 8
    int tn = (tid & 15) << 2;       // 0..60 step 4
    float acc[8][4] = {};

    for (int k0 = 0; k0 < K; k0 += 16) {
        // A tile: 128x16, each thread 8 floats = 2 float4 along k
        {
            int base = tid * 8;
            int mm = base >> 4, kk = base & 15;   // kk in {0,8}
            int r = row0 + mm;
            float4 a0 = make_float4(0.f, 0.f, 0.f, 0.f), a1 = a0;
            if (r < M) {
                a0 = *(const float4*)(A + (size_t)r * K + k0 + kk);
                a1 = *(const float4*)(A + (size_t)r * K + k0 + kk + 4);
            }
            As[kk + 0][mm] = a0.x; As[kk + 1][mm] = a0.y;
            As[kk + 2][mm] = a0.z; As[kk + 3][mm] = a0.w;
            As[kk + 4][mm] = a1.x; As[kk + 5][mm] = a1.y;
            As[kk + 6][mm] = a1.z; As[kk + 7][mm] = a1.w;
        }
        // B tile: 16x64, each thread 1 float4
        {
            int base = tid * 4;
            int kk = base >> 6, nn = base & 63;
            float4 bv = *(const float4*)(B + (size_t)(k0 + kk) * Ncol + col0 + nn);
            Bs[kk][nn] = bv.x; Bs[kk][nn + 1] = bv.y;
            Bs[kk][nn + 2] = bv.z; Bs[kk][nn + 3] = bv.w;
        }
        __syncthreads();
        #pragma unroll
        for (int kk = 0; kk < 16; kk++) {
            float4 a0 = *(const float4*)&As[kk][tm];
            float4 a1 = *(const float4*)&As[kk][tm + 4];
            float4 bv = *(const float4*)&Bs[kk][tn];
            float a[8] = {a0.x, a0.y, a0.z, a0.w, a1.x, a1.y, a1.z, a1.w};
            float b[4] = {bv.x, bv.y, bv.z, bv.w};
            #pragma unroll
            for (int i = 0; i < 8; i++)
                #pragma unroll
                for (int j = 0; j < 4; j++)
                    acc[i][j] += a[i] * b[j];
        }
        __syncthreads();
    }
    #pragma unroll
    for (int i = 0; i < 8; i++) {
        int r = row0 + tm + i;
        if (r < M) {
            float4 v = make_float4(acc[i][0], acc[i][1], acc[i][2], acc[i][3]);
            *(float4*)(C + (size_t)r * Ncol + col0 + tn) = v;
        }
    }
}

// ---------------- per-node attention coefficients ----------------
__global__ void alpha1_kernel(const float* __restrict__ a_src,
                              const float* __restrict__ a_dst) {
    int i = blockIdx.x * blockDim.x + threadIdx.x;
    if (i >= N_ * HEADS) return;
    int n = i >> 3, h = i & 7;
    const float4* hp = (const float4*)(g_h1 + (size_t)n * F1 + h * HID);
    const float4* sp = (const float4*)(a_src + h * HID);
    const float4* dp = (const float4*)(a_dst + h * HID);
    float s = 0.f, d = 0.f;
    #pragma unroll
    for (int q = 0; q < HID / 4; q++) {
        float4 hv = hp[q], sv = sp[q], dv = dp[q];
        s += hv.x * sv.x + hv.y * sv.y + hv.z * sv.z + hv.w * sv.w;
        d += hv.x * dv.x + hv.y * dv.y + hv.z * dv.z + hv.w * dv.w;
    }
    g_as1[i] = s; g_ad1[i] = d;
}

__global__ void alpha2_kernel(const float* __restrict__ a_src,
                              const float* __restrict__ a_dst) {
    int n = blockIdx.x * blockDim.x + threadIdx.x;
    if (n >= N_) return;
    const float4* hp = (const float4*)(g_h2 + (size_t)n * OUTC);
    const float4* sp = (const float4*)a_src;
    const float4* dp = (const float4*)a_dst;
    float s = 0.f, d = 0.f;
    #pragma unroll
    for (int q = 0; q < OUTC / 4; q++) {
        float4 hv = hp[q], sv = sp[q], dv = dp[q];
        s += hv.x * sv.x + hv.y * sv.y + hv.z * sv.z + hv.w * sv.w;
        d += hv.x * dv.x + hv.y * dv.y + hv.z * dv.z + hv.w * dv.w;
    }
    g_as2[n] = s; g_ad2[n] = d;
}

// ---------------- CSR aggregation layer 1: one warp per dst node ----------
// lane owns channels c = lane*8 + q (q=0..7) -> head h = lane>>2 (fixed/lane)
// softmax without max-shift: shift-invariant; logits are O(1) here (no overflow)
__global__ void aggregate1(const float* __restrict__ b1) {
    __shared__ int   ss[8][32];
    __shared__ float ws[8][32][8];
    int w = (blockIdx.x * blockDim.x + threadIdx.x) >> 5;
    if (w >= N_) return;
    int lane = threadIdx.x & 31;
    int wb   = (threadIdx.x >> 5) & 7;
    int beg = g_roff[w], end = g_roff[w + 1];

    float ad[8];
    {
        float4 d0 = *(const float4*)(g_ad1 + w * 8);
        float4 d1 = *(const float4*)(g_ad1 + w * 8 + 4);
        ad[0] = d0.x; ad[1] = d0.y; ad[2] = d0.z; ad[3] = d0.w;
        ad[4] = d1.x; ad[5] = d1.y; ad[6] = d1.z; ad[7] = d1.w;
    }

    float acc[8] = {};
    float zp[8]  = {};

    for (int base = beg; base < end; base += 32) {
        int cnt = min(32, end - base);
        __syncwarp();   // WAR vs previous chunk's reads
        if (base + lane < end) {
            int s = g_csr_src[base + lane];
            ss[wb][lane] = s;
            float4 s0 = *(const float4*)(g_as1 + s * 8);
            float4 s1 = *(const float4*)(g_as1 + s * 8 + 4);
            float ev[8] = {s0.x + ad[0], s0.y + ad[1], s0.z + ad[2], s0.w + ad[3],
                           s1.x + ad[4], s1.y + ad[5], s1.z + ad[6], s1.w + ad[7]};
            #pragma unroll
            for (int h = 0; h < 8; h++) {
                float e = ev[h];
                e = (e >= 0.f) ? e : NEG_SLOPE * e;
                float wv = __expf(e);
                ws[wb][lane][h] = wv;
                zp[h] += wv;
            }
        }
        __syncwarp();
        for (int j = 0; j < cnt; j++) {
            int s = ss[wb][j];
            float wj = ws[wb][j][lane >> 2];
            const float* hs = g_h1 + (size_t)s * F1 + lane * 8;
            float4 p0 = *(const float4*)hs;
            float4 p1 = *(const float4*)(hs + 4);
            acc[0] += wj * p0.x; acc[1] += wj * p0.y;
            acc[2] += wj * p0.z; acc[3] += wj * p0.w;
            acc[4] += wj * p1.x; acc[5] += wj * p1.y;
            acc[6] += wj * p1.z; acc[7] += wj * p1.w;
        }
    }

    // reduce z across warp (all 8 heads)
    #pragma unroll
    for (int h = 0; h < 8; h++)
        #pragma unroll
        for (int off = 16; off > 0; off >>= 1)
            zp[h] += __shfl_xor_sync(0xffffffffu, zp[h], off);
    float zu = zp[0];
    #pragma unroll
    for (int h = 1; h < 8; h++)
        if ((lane >> 2) == h) zu = zp[h];

    float inv = (zu > 0.f) ? (1.f / zu) : 0.f;
    const float* bp = b1 + lane * 8;
    float4 b0 = *(const float4*)bp;
    float4 b1v = *(const float4*)(bp + 4);
    float bb[8] = {b0.x, b0.y, b0.z, b0.w, b1v.x, b1v.y, b1v.z, b1v.w};
    float o[8];
    #pragma unroll
    for (int q = 0; q < 8; q++) {
        float v = acc[q] * inv + bb[q];
        o[q] = (v > 0.f) ? v : (__expf(v) - 1.f);   // ELU
    }
    float* op = g_hact + (size_t)w * F1 + lane * 8;
    *(float4*)op       = make_float4(o[0], o[1], o[2], o[3]);
    *(float4*)(op + 4) = make_float4(o[4], o[5], o[6], o[7]);
}

// ---------------- CSR aggregation layer 2: one warp per dst node ----------
// lane owns channels c = lane*2, lane*2+1
__global__ void aggregate2(const float* __restrict__ b2, float* __restrict__ out) {
    __shared__ int   ss[8][32];
    __shared__ float ws[8][32];
    int w = (blockIdx.x * blockDim.x + threadIdx.x) >> 5;
    if (w >= N_) return;
    int lane = threadIdx.x & 31;
    int wb   = (threadIdx.x >> 5) & 7;
    int beg = g_roff[w], end = g_roff[w + 1];
    float adn = g_ad2[w];

    float acc0 = 0.f, acc1 = 0.f, zp = 0.f;

    for (int base = beg; base < end; base += 32) {
        int cnt = min(32, end - base);
        __syncwarp();
        if (base + lane < end) {
            int s = g_csr_src[base + lane];
            ss[wb][lane] = s;
            float e = g_as2[s] + adn;
            e = (e >= 0.f) ? e : NEG_SLOPE * e;
            float wv = __expf(e);
            ws[wb][lane] = wv;
            zp += wv;
        }
        __syncwarp();
        for (int j = 0; j < cnt; j++) {
            int s = ss[wb][j];
            float wj = ws[wb][j];
            float2 hv = *(const float2*)(g_h2 + (size_t)s * OUTC + lane * 2);
            acc0 += wj * hv.x;
            acc1 += wj * hv.y;
        }
    }
    #pragma unroll
    for (int off = 16; off > 0; off >>= 1)
        zp += __shfl_xor_sync(0xffffffffu, zp, off);
    float inv = (zp > 0.f) ? (1.f / zp) : 0.f;
    float2 bv = *(const float2*)(b2 + lane * 2);
    float2 ov = make_float2(acc0 * inv + bv.x, acc1 * inv + bv.y);
    *(float2*)(out + (size_t)w * OUTC + lane * 2) = ov;
}

// ---------------- launch ----------------
extern "C" void kernel_launch(void* const* d_in, const int* in_sizes, int n_in,
                              void* d_out, int out_size) {
    const float* x    = (const float*)d_in[0];
    const int*   ei32 = (const int*)d_in[1];
    const float* W1   = (const float*)d_in[2];
    const float* a1s  = (const float*)d_in[3];
    const float* a1d  = (const float*)d_in[4];
    const float* b1   = (const float*)d_in[5];
    const float* W2   = (const float*)d_in[6];
    const float* a2s  = (const float*)d_in[7];
    const float* a2d  = (const float*)d_in[8];
    const float* b2   = (const float*)d_in[9];
    float* out = (float*)d_out;

    void* p;
    cudaGetSymbolAddress(&p, g_h1);   float* h1   = (float*)p;
    cudaGetSymbolAddress(&p, g_hact); float* hact = (float*)p;
    cudaGetSymbolAddress(&p, g_h2);   float* h2   = (float*)p;

    // graph build (CSR) — fully parallel scan
    zero_deg<<<(N_ + 1023) / 1024, 1024>>>();
    probe_edges<<<1, 32>>>(ei32);
    conv_edges<<<(E_ + 255) / 256, 256>>>(ei32);
    scan_p1<<<NB_SCAN, 256>>>();
    scan_p2<<<1, 256>>>();
    scan_p3<<<NB_SCAN, 256>>>();
    build_csr<<<(E_ + 255) / 256, 256>>>();

    // layer 1
    {
        dim3 grid(F1 / 64, (N_ + 127) / 128);
        sgemm128x64<<<grid, 256>>>(x, W1, h1, N_, INC, F1);
    }
    alpha1_kernel<<<(N_ * HEADS + 255) / 256, 256>>>(a1s, a1d);
    aggregate1<<<(N_ * 32 + 255) / 256, 256>>>(b1);

    // layer 2
    {
        dim3 grid(OUTC / 64, (N_ + 127) / 128);
        sgemm128x64<<<grid, 256>>>(hact, W2, h2, N_, F1, OUTC);
    }
    alpha2_kernel<<<(N_ + 255) / 256, 256>>>(a2s, a2d);
    aggregate2<<<(N_ * 32 + 255) / 256, 256>>>(b2, out);
}